// round 6
// baseline (speedup 1.0000x reference)
#include <cuda_runtime.h>

#define NTHREADS 256
#define TB 8
#define EDIM 1024
#define NQ 8

typedef unsigned long long u64;

__device__ __forceinline__ u64 pack2(float lo, float hi) {
    u64 r; asm("mov.b64 %0, {%1, %2};" : "=l"(r) : "f"(lo), "f"(hi)); return r;
}
__device__ __forceinline__ u64 packdup(float v) {
    u64 r; asm("mov.b64 %0, {%1, %1};" : "=l"(r) : "f"(v)); return r;
}
__device__ __forceinline__ void unpack2(u64 p, float& lo, float& hi) {
    asm("mov.b64 {%0, %1}, %2;" : "=f"(lo), "=f"(hi) : "l"(p));
}
__device__ __forceinline__ u64 mul2(u64 a, u64 b) {
    u64 r; asm("mul.rn.f32x2 %0, %1, %2;" : "=l"(r) : "l"(a), "l"(b)); return r;
}
__device__ __forceinline__ u64 fma2(u64 a, u64 b, u64 c) {
    u64 r; asm("fma.rn.f32x2 %0, %1, %2, %3;" : "=l"(r) : "l"(a), "l"(b), "l"(c)); return r;
}
__device__ __forceinline__ u64 add2(u64 a, u64 b) {
    u64 r; asm("add.rn.f32x2 %0, %1, %2;" : "=l"(r) : "l"(a), "l"(b)); return r;
}

// psum class arrays (u64), each [TB tokens][128 entries] = 8 KB:
//   A: pair0 (qubits 0,1)   B: pair1 (qubits 2,3)   written by even threads
//   C: pair2 (qubits 4,5)   D: pair3 (qubits 6,7)   written by odd threads
// C,D shifted +64B so even/odd STS lanes and class LDS phases hit disjoint banks.
#define A_OFF 0u
#define B_OFF 8192u
#define C_OFF (16384u + 64u)
#define D_OFF (24576u + 64u)
#define PSUM_BYTES (32768u + 128u)
#define ZDUP_FLOAT (PSUM_BYTES/4)            // zdup: TB*16 floats
#define SMEM_FLOATS (ZDUP_FLOAT + TB*16 + 16)

__global__ __launch_bounds__(NTHREADS, 2)
void qff_fused(const float* __restrict__ x,
               const float* __restrict__ W_in,
               const float* __restrict__ b_in,
               const float* __restrict__ theta,
               const float* __restrict__ W_out,
               const float* __restrict__ b_out,
               float* __restrict__ out,
               int n_tokens)
{
    extern __shared__ float sm[];
    char* smc  = reinterpret_cast<char*>(sm);
    float* zdup = sm + ZDUP_FLOAT;
    float* cth  = zdup + TB*16;
    float* bi   = cth + 8;

    const int tid  = threadIdx.x;
    const int lane = tid & 31;
    const int wrp  = tid >> 5;
    const int odd  = tid & 1;

    if (tid < NQ) { cth[tid] = cosf(theta[tid]); bi[tid] = b_in[tid]; }

    // ---- W_in pairs in parity-permuted order: K0,K1 kept; S0,S1 sent to partner ----
    // even: K0=pair0 K1=pair1 S0=pair2 S1=pair3 ; odd: K0=pair2 K1=pair3 S0=pair0 S1=pair1
    u64 wiK0[4], wiK1[4], wiS0[4], wiS1[4];
    {
        const int pk0 = odd ? 2 : 0, pk1 = odd ? 3 : 1;
        const int ps0 = odd ? 0 : 2, ps1 = odd ? 1 : 3;
        #define LOADPAIR(dst, pr) { \
            float4 wa = reinterpret_cast<const float4*>(W_in + (2*(pr)  )*EDIM)[tid]; \
            float4 wb = reinterpret_cast<const float4*>(W_in + (2*(pr)+1)*EDIM)[tid]; \
            dst[0]=pack2(wa.x,wb.x); dst[1]=pack2(wa.y,wb.y); \
            dst[2]=pack2(wa.z,wb.z); dst[3]=pack2(wa.w,wb.w); }
        LOADPAIR(wiK0, pk0) LOADPAIR(wiK1, pk1)
        LOADPAIR(wiS0, ps0) LOADPAIR(wiS1, ps1)
        #undef LOADPAIR
    }
    // ---- W_out pairs (as R5) ----
    u64 wo01[8], wo23[8];
    {
        float4 rA[4], rB[4];
#pragma unroll
        for (int j = 0; j < 4; j++) {
            rA[j] = reinterpret_cast<const float4*>(W_out)[(4*tid+j)*2 + 0];
            rB[j] = reinterpret_cast<const float4*>(W_out)[(4*tid+j)*2 + 1];
        }
        wo01[0]=pack2(rA[0].x,rA[1].x); wo01[1]=pack2(rA[0].y,rA[1].y);
        wo01[2]=pack2(rA[0].z,rA[1].z); wo01[3]=pack2(rA[0].w,rA[1].w);
        wo01[4]=pack2(rB[0].x,rB[1].x); wo01[5]=pack2(rB[0].y,rB[1].y);
        wo01[6]=pack2(rB[0].z,rB[1].z); wo01[7]=pack2(rB[0].w,rB[1].w);
        wo23[0]=pack2(rA[2].x,rA[3].x); wo23[1]=pack2(rA[2].y,rA[3].y);
        wo23[2]=pack2(rA[2].z,rA[3].z); wo23[3]=pack2(rA[2].w,rA[3].w);
        wo23[4]=pack2(rB[2].x,rB[3].x); wo23[5]=pack2(rB[2].y,rB[3].y);
        wo23[6]=pack2(rB[2].z,rB[3].z); wo23[7]=pack2(rB[2].w,rB[3].w);
    }
    u64 bo01, bo23;
    { float4 bo = reinterpret_cast<const float4*>(b_out)[tid];
      bo01 = pack2(bo.x, bo.y); bo23 = pack2(bo.z, bo.w); }

    // per-thread psum store pointers (even -> A/B, odd -> C/D), entry k = tid>>1
    u64* stP = reinterpret_cast<u64*>(smc + (odd ? C_OFF : A_OFF)) + (tid >> 1);
    u64* stQ = reinterpret_cast<u64*>(smc + (odd ? D_OFF : B_OFF)) + (tid >> 1);

    // stage-2 lane constants
    const int pr2 = lane >> 3;
    const int c8  = lane & 7;
    const unsigned cls = (pr2 == 0) ? A_OFF : (pr2 == 1) ? B_OFF
                       : (pr2 == 2) ? C_OFF : D_OFF;
    const u64* s2base = reinterpret_cast<const u64*>(smc + cls) + wrp*128 + c8;
    const int jst = pr2 & 1;                 // class-parity stagger

    const int nbatches = n_tokens / TB;
    const int stride   = gridDim.x;
    const float4* x4 = reinterpret_cast<const float4*>(x);
    float4* out4 = reinterpret_cast<float4*>(out);

    int b = blockIdx.x;
    if (b >= nbatches) return;

    float4 xv[TB];
    #define LOADX(bb) { const float4* r = x4 + (long)(bb)*TB*(EDIM/4) + tid; \
        _Pragma("unroll") for (int t = 0; t < TB; t++) xv[t] = r[t*(EDIM/4)]; }

    #define PHASE1() { \
        _Pragma("unroll") for (int t = 0; t < TB; t++) { \
            u64 xx = packdup(xv[t].x), xy = packdup(xv[t].y); \
            u64 xz = packdup(xv[t].z), xw = packdup(xv[t].w); \
            u64 k0 = mul2(xx, wiK0[0]); k0 = fma2(xy, wiK0[1], k0); \
            k0 = fma2(xz, wiK0[2], k0); k0 = fma2(xw, wiK0[3], k0); \
            u64 k1 = mul2(xx, wiK1[0]); k1 = fma2(xy, wiK1[1], k1); \
            k1 = fma2(xz, wiK1[2], k1); k1 = fma2(xw, wiK1[3], k1); \
            u64 s0 = mul2(xx, wiS0[0]); s0 = fma2(xy, wiS0[1], s0); \
            s0 = fma2(xz, wiS0[2], s0); s0 = fma2(xw, wiS0[3], s0); \
            u64 s1 = mul2(xx, wiS1[0]); s1 = fma2(xy, wiS1[1], s1); \
            s1 = fma2(xz, wiS1[2], s1); s1 = fma2(xw, wiS1[3], s1); \
            u64 r0 = __shfl_xor_sync(0xffffffffu, s0, 1); \
            u64 r1 = __shfl_xor_sync(0xffffffffu, s1, 1); \
            stP[t*128] = add2(k0, r0); \
            stQ[t*128] = add2(k1, r1); \
        } }

    #define STAGE2(bb) { \
        u64 a0 = s2base[8*(( 0+jst)&15)], a1 = s2base[8*(( 1+jst)&15)]; \
        u64 a2 = s2base[8*(( 2+jst)&15)], a3 = s2base[8*(( 3+jst)&15)]; \
        _Pragma("unroll") for (int j = 4; j < 16; j += 4) { \
            a0 = add2(a0, s2base[8*((j+0+jst)&15)]); \
            a1 = add2(a1, s2base[8*((j+1+jst)&15)]); \
            a2 = add2(a2, s2base[8*((j+2+jst)&15)]); \
            a3 = add2(a3, s2base[8*((j+3+jst)&15)]); \
        } \
        u64 acc = add2(add2(a0, a1), add2(a2, a3)); \
        acc = add2(acc, __shfl_down_sync(0xffffffffu, acc, 4, 8)); \
        acc = add2(acc, __shfl_down_sync(0xffffffffu, acc, 2, 8)); \
        acc = add2(acc, __shfl_down_sync(0xffffffffu, acc, 1, 8)); \
        float sa, sb; unpack2(acc, sa, sb); \
        float ma = cth[2*pr2  ] * cosf(sa + bi[2*pr2  ]); \
        float mb = cth[2*pr2+1] * cosf(sb + bi[2*pr2+1]); \
        float pp = ma * mb; \
        float incl = pp, tt; \
        tt = __shfl_up_sync(0xffffffffu, incl, 8);  if (lane >= 8)  incl *= tt; \
        tt = __shfl_up_sync(0xffffffffu, incl, 16); if (lane >= 16) incl *= tt; \
        float E = __shfl_up_sync(0xffffffffu, incl, 8); \
        if (pr2 == 0) E = 1.0f; \
        float za = E * ma, zb = E * pp; \
        if (c8 == 0) \
            reinterpret_cast<float4*>(zdup + wrp*16)[pr2] = make_float4(za, za, zb, zb); \
        }

    #define PHASE3(bb) { \
        float4* orow = out4 + (long)(bb)*TB*(EDIM/4) + tid; \
        _Pragma("unroll") for (int t = 0; t < TB; t++) { \
            const ulonglong2* zr = reinterpret_cast<const ulonglong2*>(zdup + t*16); \
            ulonglong2 z01 = zr[0], z23 = zr[1], z45 = zr[2], z67 = zr[3]; \
            u64 acc01 = bo01, acc23 = bo23; \
            acc01 = fma2(z01.x, wo01[0], acc01);  acc23 = fma2(z01.x, wo23[0], acc23); \
            acc01 = fma2(z01.y, wo01[1], acc01);  acc23 = fma2(z01.y, wo23[1], acc23); \
            acc01 = fma2(z23.x, wo01[2], acc01);  acc23 = fma2(z23.x, wo23[2], acc23); \
            acc01 = fma2(z23.y, wo01[3], acc01);  acc23 = fma2(z23.y, wo23[3], acc23); \
            acc01 = fma2(z45.x, wo01[4], acc01);  acc23 = fma2(z45.x, wo23[4], acc23); \
            acc01 = fma2(z45.y, wo01[5], acc01);  acc23 = fma2(z45.y, wo23[5], acc23); \
            acc01 = fma2(z67.x, wo01[6], acc01);  acc23 = fma2(z67.x, wo23[6], acc23); \
            acc01 = fma2(z67.y, wo01[7], acc01);  acc23 = fma2(z67.y, wo23[7], acc23); \
            float a0, a1, a2, a3; \
            unpack2(acc01, a0, a1); unpack2(acc23, a2, a3); \
            orow[t*(EDIM/4)] = make_float4(fmaxf(a0,0.f), fmaxf(a1,0.f), \
                                           fmaxf(a2,0.f), fmaxf(a3,0.f)); \
        } }

    // ---- prologue: fill pipeline for batch b ----
    LOADX(b);
    PHASE1();                     // psum(b)
    {
        int b1 = b + stride; if (b1 >= nbatches) b1 = b;
        LOADX(b1);                // xv <- x(b+stride)
    }
    __syncthreads();              // cth/bi + psum(b) ready
    STAGE2(b);                    // zdup(b)

    // ---- steady state: per iter, phase1(b+1)+phase3(b) then stage2(b+1) ----
    for (;;) {
        int bn = b + stride;
        bool more = (bn < nbatches);
        __syncthreads();          // syncB: zdup(b) visible; stage2 done reading psum
        if (more) {
            PHASE1();             // psum(bn), consumes xv
            int b2 = bn + stride; if (b2 >= nbatches) b2 = bn;
            LOADX(b2);            // prefetch
        }
        PHASE3(b);                // reads zdup(b)
        if (!more) break;
        __syncthreads();          // syncA: psum(bn) ready; zdup(b) reads done
        STAGE2(bn);               // writes zdup(bn)
        b = bn;
    }

    #undef LOADX
    #undef PHASE1
    #undef STAGE2
    #undef PHASE3
}

extern "C" void kernel_launch(void* const* d_in, const int* in_sizes, int n_in,
                              void* d_out, int out_size) {
    const float* x     = (const float*)d_in[0];
    const float* W_in  = (const float*)d_in[1];
    const float* b_in  = (const float*)d_in[2];
    const float* theta = (const float*)d_in[3];
    const float* W_out = (const float*)d_in[4];
    const float* b_out = (const float*)d_in[5];
    float* out = (float*)d_out;

    const int n_tokens = in_sizes[0] / EDIM;   // 32768

    const size_t smem = SMEM_FLOATS * sizeof(float);   // ~33.5 KB
    cudaFuncSetAttribute(qff_fused, cudaFuncAttributeMaxDynamicSharedMemorySize, (int)smem);
    qff_fused<<<296, NTHREADS, smem>>>(x, W_in, b_in, theta, W_out, b_out, out, n_tokens);
}

// round 9
// speedup vs baseline: 1.0914x; 1.0914x over previous
#include <cuda_runtime.h>

#define NTHREADS 256
#define TB 8
#define EDIM 1024
#define NQ 8

typedef unsigned long long u64;

__device__ __forceinline__ u64 pack2(float lo, float hi) {
    u64 r; asm("mov.b64 %0, {%1, %2};" : "=l"(r) : "f"(lo), "f"(hi)); return r;
}
__device__ __forceinline__ u64 packdup(float v) {
    u64 r; asm("mov.b64 %0, {%1, %1};" : "=l"(r) : "f"(v)); return r;
}
__device__ __forceinline__ void unpack2(u64 p, float& lo, float& hi) {
    asm("mov.b64 {%0, %1}, %2;" : "=f"(lo), "=f"(hi) : "l"(p));
}
__device__ __forceinline__ u64 mul2(u64 a, u64 b) {
    u64 r; asm("mul.rn.f32x2 %0, %1, %2;" : "=l"(r) : "l"(a), "l"(b)); return r;
}
__device__ __forceinline__ u64 fma2(u64 a, u64 b, u64 c) {
    u64 r; asm("fma.rn.f32x2 %0, %1, %2, %3;" : "=l"(r) : "l"(a), "l"(b), "l"(c)); return r;
}
__device__ __forceinline__ u64 add2(u64 a, u64 b) {
    u64 r; asm("add.rn.f32x2 %0, %1, %2;" : "=l"(r) : "l"(a), "l"(b)); return r;
}

// One psum buffer (R6 layout): 4 class arrays of [TB][128] u64 (8 KB each):
//   A: qubits 0,1   B: 2,3 (even threads)   C: 4,5   D: 6,7 (odd threads)
// C,D shifted +64B for conflict-free even/odd STS and class LDS phases.
#define A_OFF 0u
#define B_OFF 8192u
#define C_OFF (16384u + 64u)
#define D_OFF (24576u + 64u)
#define PSUM_STRIDE 32896u              // one buffer incl. pad (128B-aligned)
#define ZD_OFF   (2u * PSUM_STRIDE)     // two zdup buffers, 512 B each
#define CTH_OFF  (ZD_OFF + 1024u)
#define BI_OFF   (CTH_OFF + 32u)
#define SMEM_BYTES (BI_OFF + 32u)       // 66,880 B -> 2 CTAs/SM

__global__ __launch_bounds__(NTHREADS, 2)
void qff_fused(const float* __restrict__ x,
               const float* __restrict__ W_in,
               const float* __restrict__ b_in,
               const float* __restrict__ theta,
               const float* __restrict__ W_out,
               const float* __restrict__ b_out,
               float* __restrict__ out,
               int n_tokens)
{
    extern __shared__ char smc[];
    float* cth = reinterpret_cast<float*>(smc + CTH_OFF);
    float* bi  = reinterpret_cast<float*>(smc + BI_OFF);

    const int tid  = threadIdx.x;
    const int lane = tid & 31;
    const int wrp  = tid >> 5;
    const int odd  = tid & 1;

    if (tid < NQ) { cth[tid] = cosf(theta[tid]); bi[tid] = b_in[tid]; }

    // ---- W_in pairs, parity-permuted (K kept, S shfl'd to partner) ----
    u64 wiK0[4], wiK1[4], wiS0[4], wiS1[4];
    {
        const int pk0 = odd ? 2 : 0, pk1 = odd ? 3 : 1;
        const int ps0 = odd ? 0 : 2, ps1 = odd ? 1 : 3;
        #define LOADPAIR(dst, pr) { \
            float4 wa_ = reinterpret_cast<const float4*>(W_in + (2*(pr)  )*EDIM)[tid]; \
            float4 wb_ = reinterpret_cast<const float4*>(W_in + (2*(pr)+1)*EDIM)[tid]; \
            dst[0]=pack2(wa_.x,wb_.x); dst[1]=pack2(wa_.y,wb_.y); \
            dst[2]=pack2(wa_.z,wb_.z); dst[3]=pack2(wa_.w,wb_.w); }
        LOADPAIR(wiK0, pk0) LOADPAIR(wiK1, pk1)
        LOADPAIR(wiS0, ps0) LOADPAIR(wiS1, ps1)
        #undef LOADPAIR
    }
    // ---- W_out pairs + bias (as R5/R6) ----
    u64 wo01[8], wo23[8], bo01, bo23;
    {
        float4 rA[4], rB[4];
#pragma unroll
        for (int j = 0; j < 4; j++) {
            rA[j] = reinterpret_cast<const float4*>(W_out)[(4*tid+j)*2 + 0];
            rB[j] = reinterpret_cast<const float4*>(W_out)[(4*tid+j)*2 + 1];
        }
        wo01[0]=pack2(rA[0].x,rA[1].x); wo01[1]=pack2(rA[0].y,rA[1].y);
        wo01[2]=pack2(rA[0].z,rA[1].z); wo01[3]=pack2(rA[0].w,rA[1].w);
        wo01[4]=pack2(rB[0].x,rB[1].x); wo01[5]=pack2(rB[0].y,rB[1].y);
        wo01[6]=pack2(rB[0].z,rB[1].z); wo01[7]=pack2(rB[0].w,rB[1].w);
        wo23[0]=pack2(rA[2].x,rA[3].x); wo23[1]=pack2(rA[2].y,rA[3].y);
        wo23[2]=pack2(rA[2].z,rA[3].z); wo23[3]=pack2(rA[2].w,rA[3].w);
        wo23[4]=pack2(rB[2].x,rB[3].x); wo23[5]=pack2(rB[2].y,rB[3].y);
        wo23[6]=pack2(rB[2].z,rB[3].z); wo23[7]=pack2(rB[2].w,rB[3].w);
        float4 bo = reinterpret_cast<const float4*>(b_out)[tid];
        bo01 = pack2(bo.x, bo.y); bo23 = pack2(bo.z, bo.w);
    }

    // per-thread psum store offsets (within a buffer)
    const unsigned stP_off = (odd ? C_OFF : A_OFF) + (unsigned)(tid >> 1) * 8u;
    const unsigned stQ_off = (odd ? D_OFF : B_OFF) + (unsigned)(tid >> 1) * 8u;

    // stage-2 lane constants
    const int pr2 = lane >> 3;
    const int c8  = lane & 7;
    const unsigned cls = (pr2 == 0) ? A_OFF : (pr2 == 1) ? B_OFF
                       : (pr2 == 2) ? C_OFF : D_OFF;
    const unsigned s2_off = cls + (unsigned)wrp * 1024u + (unsigned)c8 * 8u;
    const int jst = pr2 & 1;

    const int nbatches = n_tokens / TB;
    const int stride   = gridDim.x;
    const int blk      = blockIdx.x;
    const int M = (nbatches - blk + stride - 1) / stride;   // batches this CTA (>=1)

    const float4* x4 = reinterpret_cast<const float4*>(x);
    float4* out4 = reinterpret_cast<float4*>(out);

    float4 xv[TB];
    #define LOADX(bb) { const float4* xr_ = x4 + (long)(bb)*TB*(EDIM/4) + tid; \
        _Pragma("unroll") for (int t_ = 0; t_ < TB; t_++) xv[t_] = xr_[t_*(EDIM/4)]; }

    if (blk < nbatches) LOADX(blk);   // xv <- batch 0

    for (int r = 0; r <= M + 1; r++) {
        const int par = r & 1;
        char* psumW = smc + (par ? PSUM_STRIDE : 0u);          // phase1 writes buf[par]
        char* psumR = smc + (par ? 0u : PSUM_STRIDE);          // stage2 reads buf[par^1]
        float* zdW  = reinterpret_cast<float*>(smc + ZD_OFF + (par ? 512u : 0u));
        float* zdR  = reinterpret_cast<float*>(smc + ZD_OFF + (par ? 0u : 512u));

        // ---- phase 1 on batch r (writes psum[par]), then prefetch batch r+1 ----
        if (r < M) {
#pragma unroll
            for (int t = 0; t < TB; t++) {
                u64 xx = packdup(xv[t].x), xy = packdup(xv[t].y);
                u64 xz = packdup(xv[t].z), xw = packdup(xv[t].w);
                u64 k0 = mul2(xx, wiK0[0]); k0 = fma2(xy, wiK0[1], k0);
                k0 = fma2(xz, wiK0[2], k0); k0 = fma2(xw, wiK0[3], k0);
                u64 k1 = mul2(xx, wiK1[0]); k1 = fma2(xy, wiK1[1], k1);
                k1 = fma2(xz, wiK1[2], k1); k1 = fma2(xw, wiK1[3], k1);
                u64 s0 = mul2(xx, wiS0[0]); s0 = fma2(xy, wiS0[1], s0);
                s0 = fma2(xz, wiS0[2], s0); s0 = fma2(xw, wiS0[3], s0);
                u64 s1 = mul2(xx, wiS1[0]); s1 = fma2(xy, wiS1[1], s1);
                s1 = fma2(xz, wiS1[2], s1); s1 = fma2(xw, wiS1[3], s1);
                u64 r0 = __shfl_xor_sync(0xffffffffu, s0, 1);
                u64 r1 = __shfl_xor_sync(0xffffffffu, s1, 1);
                *reinterpret_cast<u64*>(psumW + stP_off + t*1024u) = add2(k0, r0);
                *reinterpret_cast<u64*>(psumW + stQ_off + t*1024u) = add2(k1, r1);
            }
            if (r + 1 < M) { const int bnext = blk + (r + 1) * stride; LOADX(bnext); }
        }

        // ---- stage 2 on batch r-1 (reads psum[par^1], writes zdup[par]) ----
        if (r >= 1 && r - 1 < M) {
            const char* sb = psumR + s2_off;
            u64 a0 = *reinterpret_cast<const u64*>(sb + 64u*((0+jst)&15));
            u64 a1 = *reinterpret_cast<const u64*>(sb + 64u*((1+jst)&15));
            u64 a2 = *reinterpret_cast<const u64*>(sb + 64u*((2+jst)&15));
            u64 a3 = *reinterpret_cast<const u64*>(sb + 64u*((3+jst)&15));
#pragma unroll
            for (int j = 4; j < 16; j += 4) {
                a0 = add2(a0, *reinterpret_cast<const u64*>(sb + 64u*((j+0+jst)&15)));
                a1 = add2(a1, *reinterpret_cast<const u64*>(sb + 64u*((j+1+jst)&15)));
                a2 = add2(a2, *reinterpret_cast<const u64*>(sb + 64u*((j+2+jst)&15)));
                a3 = add2(a3, *reinterpret_cast<const u64*>(sb + 64u*((j+3+jst)&15)));
            }
            u64 acc = add2(add2(a0, a1), add2(a2, a3));
            acc = add2(acc, __shfl_down_sync(0xffffffffu, acc, 4, 8));
            acc = add2(acc, __shfl_down_sync(0xffffffffu, acc, 2, 8));
            acc = add2(acc, __shfl_down_sync(0xffffffffu, acc, 1, 8));
            float sa, sb2; unpack2(acc, sa, sb2);
            float ma = cth[2*pr2  ] * cosf(sa  + bi[2*pr2  ]);
            float mb = cth[2*pr2+1] * cosf(sb2 + bi[2*pr2+1]);
            float pp = ma * mb;
            float incl = pp, tt;
            tt = __shfl_up_sync(0xffffffffu, incl, 8);  if (lane >= 8)  incl *= tt;
            tt = __shfl_up_sync(0xffffffffu, incl, 16); if (lane >= 16) incl *= tt;
            float E = __shfl_up_sync(0xffffffffu, incl, 8);
            if (pr2 == 0) E = 1.0f;
            float za = E * ma, zb = E * pp;
            if (c8 == 0)
                reinterpret_cast<float4*>(zdW + wrp*16)[pr2] = make_float4(za, za, zb, zb);
        }

        // ---- phase 3 on batch r-2 (reads zdup[par^1]) ----
        if (r >= 2) {
            const int bb = blk + (r - 2) * stride;
            float4* orow = out4 + (long)bb * TB * (EDIM/4) + tid;
#pragma unroll
            for (int t = 0; t < TB; t++) {
                const ulonglong2* zr = reinterpret_cast<const ulonglong2*>(zdR + t*16);
                ulonglong2 z01 = zr[0], z23 = zr[1], z45 = zr[2], z67 = zr[3];
                u64 acc01 = bo01, acc23 = bo23;
                acc01 = fma2(z01.x, wo01[0], acc01);  acc23 = fma2(z01.x, wo23[0], acc23);
                acc01 = fma2(z01.y, wo01[1], acc01);  acc23 = fma2(z01.y, wo23[1], acc23);
                acc01 = fma2(z23.x, wo01[2], acc01);  acc23 = fma2(z23.x, wo23[2], acc23);
                acc01 = fma2(z23.y, wo01[3], acc01);  acc23 = fma2(z23.y, wo23[3], acc23);
                acc01 = fma2(z45.x, wo01[4], acc01);  acc23 = fma2(z45.x, wo23[4], acc23);
                acc01 = fma2(z45.y, wo01[5], acc01);  acc23 = fma2(z45.y, wo23[5], acc23);
                acc01 = fma2(z67.x, wo01[6], acc01);  acc23 = fma2(z67.x, wo23[6], acc23);
                acc01 = fma2(z67.y, wo01[7], acc01);  acc23 = fma2(z67.y, wo23[7], acc23);
                float a0, a1, a2, a3;
                unpack2(acc01, a0, a1); unpack2(acc23, a2, a3);
                orow[t*(EDIM/4)] = make_float4(fmaxf(a0,0.f), fmaxf(a1,0.f),
                                               fmaxf(a2,0.f), fmaxf(a3,0.f));
            }
        }

        __syncthreads();   // single barrier: separates all cross-region hazards
    }
    #undef LOADX
}

extern "C" void kernel_launch(void* const* d_in, const int* in_sizes, int n_in,
                              void* d_out, int out_size) {
    const float* x     = (const float*)d_in[0];
    const float* W_in  = (const float*)d_in[1];
    const float* b_in  = (const float*)d_in[2];
    const float* theta = (const float*)d_in[3];
    const float* W_out = (const float*)d_in[4];
    const float* b_out = (const float*)d_in[5];
    float* out = (float*)d_out;

    const int n_tokens = in_sizes[0] / EDIM;   // 32768

    cudaFuncSetAttribute(qff_fused, cudaFuncAttributeMaxDynamicSharedMemorySize,
                         (int)SMEM_BYTES);
    qff_fused<<<296, NTHREADS, SMEM_BYTES>>>(x, W_in, b_in, theta, W_out, b_out,
                                             out, n_tokens);
}